// round 3
// baseline (speedup 1.0000x reference)
#include <cuda_runtime.h>

#define CIN  128
#define NHW  128
#define C1   50
#define C1P  56
#define C2   18
#define BATCH 8
#define HH   512
#define WW   512

// scratch (allocation-free rule: device globals)
__device__ float g_h[BATCH * C1 * NHW * NHW];       // conv1 output (26.2 MB)
__device__ float g_cond[BATCH * C2 * NHW * NHW];    // conv2 output (9.4 MB)

__device__ __forceinline__ unsigned long long pk2(float lo, float hi) {
    unsigned long long r;
    asm("mov.b64 %0, {%1, %2};" : "=l"(r) : "f"(lo), "f"(hi));
    return r;
}
__device__ __forceinline__ void upk2(unsigned long long v, float& lo, float& hi) {
    asm("mov.b64 {%0, %1}, %2;" : "=f"(lo), "=f"(hi) : "l"(v));
}
__device__ __forceinline__ void fma2(unsigned long long& d, unsigned long long a, unsigned long long b) {
    asm("fma.rn.f32x2 %0, %1, %2, %3;" : "=l"(d) : "l"(a), "l"(b), "l"(d));
}

// ---------------------------------------------------------------------------
// conv1: ctrl [8,128,128,128] -> relu -> BN -> g_h [8,50,128,128]
// block: 32x8 pixel tile x 56 channels (50 real). 256 thr = 32 px-cols x 8 cgroups.
// thread: 8 rows x 7 channels, accumulators as packed row-pairs (f32x2).
// ---------------------------------------------------------------------------
__global__ __launch_bounds__(256, 2)
void conv1_kernel(const float* __restrict__ ctrl, const float* __restrict__ w1,
                  const float* __restrict__ b1, const float* __restrict__ gamma,
                  const float* __restrict__ beta, const float* __restrict__ mean,
                  const float* __restrict__ var)
{
    __shared__ float  s_in[8][10][34];     // 10.9 KB
    __shared__ float2 s_w[8][9][C1P];      // 32.3 KB, weights duplicated (w,w)

    const int tx = threadIdx.x & 31;
    const int cg = threadIdx.x >> 5;
    const int x0 = blockIdx.x * 32;
    const int y0 = blockIdx.y * 8;
    const int b  = blockIdx.z;

    unsigned long long acc[4][7];
#pragma unroll
    for (int j = 0; j < 4; ++j)
#pragma unroll
        for (int q = 0; q < 7; ++q) acc[j][q] = 0ULL;

    const float* ctrl_b = ctrl + (size_t)b * CIN * NHW * NHW;

    for (int ch = 0; ch < CIN; ch += 8) {
        __syncthreads();
        // stage input tile (with zero halo)
        for (int idx = threadIdx.x; idx < 8 * 10 * 34; idx += 256) {
            int c = idx / 340, rem = idx - c * 340;
            int r = rem / 34, cl = rem - r * 34;
            int y = y0 + r - 1, x = x0 + cl - 1;
            float v = 0.f;
            if ((unsigned)y < (unsigned)NHW && (unsigned)x < (unsigned)NHW)
                v = ctrl_b[(ch + c) * (NHW * NHW) + y * NHW + x];
            s_in[c][r][cl] = v;
        }
        // stage weights, duplicated into float2 so LDS.64 feeds FFMA2 directly
        for (int idx = threadIdx.x; idx < 8 * 9 * C1P; idx += 256) {
            int c = idx / (9 * C1P), rem = idx - c * (9 * C1P);
            int kk = rem / C1P, oc = rem - kk * C1P;
            float w = (oc < C1) ? w1[oc * (CIN * 9) + (ch + c) * 9 + kk] : 0.f;
            s_w[c][kk][oc] = make_float2(w, w);
        }
        __syncthreads();

#pragma unroll 1
        for (int c = 0; c < 8; ++c) {
#pragma unroll
            for (int kx = 0; kx < 3; ++kx) {
                float v[10];
#pragma unroll
                for (int r = 0; r < 10; ++r) v[r] = s_in[c][r][tx + kx];
                unsigned long long pe[5], po[4];
#pragma unroll
                for (int j = 0; j < 5; ++j) pe[j] = pk2(v[2 * j], v[2 * j + 1]);
#pragma unroll
                for (int j = 0; j < 4; ++j) po[j] = pk2(v[2 * j + 1], v[2 * j + 2]);
                const unsigned long long* wr0 = (const unsigned long long*)&s_w[c][0 * 3 + kx][cg * 7];
                const unsigned long long* wr1 = (const unsigned long long*)&s_w[c][1 * 3 + kx][cg * 7];
                const unsigned long long* wr2 = (const unsigned long long*)&s_w[c][2 * 3 + kx][cg * 7];
#pragma unroll
                for (int q = 0; q < 7; ++q) {
                    unsigned long long w0 = wr0[q];
                    fma2(acc[0][q], pe[0], w0); fma2(acc[1][q], pe[1], w0);
                    fma2(acc[2][q], pe[2], w0); fma2(acc[3][q], pe[3], w0);
                    unsigned long long w1v = wr1[q];
                    fma2(acc[0][q], po[0], w1v); fma2(acc[1][q], po[1], w1v);
                    fma2(acc[2][q], po[2], w1v); fma2(acc[3][q], po[3], w1v);
                    unsigned long long w2v = wr2[q];
                    fma2(acc[0][q], pe[1], w2v); fma2(acc[1][q], pe[2], w2v);
                    fma2(acc[2][q], pe[3], w2v); fma2(acc[3][q], pe[4], w2v);
                }
            }
        }
    }

    // epilogue: bias -> relu -> BN -> store
#pragma unroll
    for (int q = 0; q < 7; ++q) {
        int oc = cg * 7 + q;
        if (oc < C1) {
            float bb = b1[oc];
            float sc = gamma[oc] * rsqrtf(var[oc] + 1e-5f);
            float bt = beta[oc] - mean[oc] * sc;
            float* hp = g_h + (((size_t)b * C1 + oc) * NHW + y0) * NHW + x0 + tx;
#pragma unroll
            for (int j = 0; j < 4; ++j) {
                float lo, hi;
                upk2(acc[j][q], lo, hi);
                hp[(2 * j) * NHW]     = fmaxf(lo + bb, 0.f) * sc + bt;
                hp[(2 * j + 1) * NHW] = fmaxf(hi + bb, 0.f) * sc + bt;
            }
        }
    }
}

// ---------------------------------------------------------------------------
// conv2: g_h [8,50,128,128] -> g_cond [8,18,128,128]
// block: 32x32 tile, 256 thr = 32 cols x 8 row-groups; thread: 4 rows x 18 ch
// channel-pairs packed in f32x2, input duplicated per row.
// ---------------------------------------------------------------------------
__global__ __launch_bounds__(256)
void conv2_kernel(const float* __restrict__ w2, const float* __restrict__ b2)
{
    __shared__ float  s_in[5][34][34];   // 23.1 KB
    __shared__ float2 s_w[5][9][9];      // 6.5 KB (channel pairs)

    const int tx = threadIdx.x & 31;
    const int rg = threadIdx.x >> 5;
    const int x0 = blockIdx.x * 32;
    const int y0 = blockIdx.y * 32;
    const int b  = blockIdx.z;

    unsigned long long acc[4][9];
#pragma unroll
    for (int r = 0; r < 4; ++r)
#pragma unroll
        for (int q = 0; q < 9; ++q) acc[r][q] = 0ULL;

    for (int ch = 0; ch < C1; ch += 5) {
        __syncthreads();
        for (int idx = threadIdx.x; idx < 5 * 34 * 34; idx += 256) {
            int c = idx / 1156, rem = idx - c * 1156;
            int r = rem / 34, cl = rem - r * 34;
            int y = y0 + r - 1, x = x0 + cl - 1;
            float v = 0.f;
            if ((unsigned)y < (unsigned)NHW && (unsigned)x < (unsigned)NHW)
                v = g_h[(((size_t)b * C1 + ch + c) * NHW + y) * NHW + x];
            s_in[c][r][cl] = v;
        }
        for (int idx = threadIdx.x; idx < 5 * 9 * 9; idx += 256) {
            int c = idx / 81, rem = idx - c * 81;
            int kk = rem / 9, q2 = rem - kk * 9;
            s_w[c][kk][q2] = make_float2(
                w2[(2 * q2)     * (C1 * 9) + (ch + c) * 9 + kk],
                w2[(2 * q2 + 1) * (C1 * 9) + (ch + c) * 9 + kk]);
        }
        __syncthreads();

        const int rbase = rg * 4;
#pragma unroll 1
        for (int c = 0; c < 5; ++c) {
#pragma unroll
            for (int kx = 0; kx < 3; ++kx) {
                float v[6];
#pragma unroll
                for (int r = 0; r < 6; ++r) v[r] = s_in[c][rbase + r][tx + kx];
#pragma unroll
                for (int ky = 0; ky < 3; ++ky) {
                    const unsigned long long* wrow = (const unsigned long long*)&s_w[c][ky * 3 + kx][0];
                    unsigned long long iv[4];
#pragma unroll
                    for (int r = 0; r < 4; ++r) iv[r] = pk2(v[r + ky], v[r + ky]);
#pragma unroll
                    for (int q2 = 0; q2 < 9; ++q2) {
                        unsigned long long wv = wrow[q2];
                        fma2(acc[0][q2], iv[0], wv);
                        fma2(acc[1][q2], iv[1], wv);
                        fma2(acc[2][q2], iv[2], wv);
                        fma2(acc[3][q2], iv[3], wv);
                    }
                }
            }
        }
    }

#pragma unroll
    for (int q2 = 0; q2 < 9; ++q2) {
        float bl = b2[2 * q2], bh = b2[2 * q2 + 1];
        float* p0 = g_cond + (((size_t)b * C2 + 2 * q2) * NHW + y0 + rg * 4) * NHW + x0 + tx;
        float* p1 = p0 + (size_t)NHW * NHW;
#pragma unroll
        for (int r = 0; r < 4; ++r) {
            float lo, hi;
            upk2(acc[r][q2], lo, hi);
            p0[r * NHW] = lo + bl;
            p1[r * NHW] = hi + bh;
        }
    }
}

// ---------------------------------------------------------------------------
// dynamic 9-tap cell-strided filter.
// out[b,ch,y,x] = sum_k img[b,ch, y+(j-1)*4, x+(i-1)*4] * cond[b, g*9+k, y/4, x/4]
// k = i*3 + j, g = ch/3. One thread per float4 (4-aligned -> all taps aligned).
// ---------------------------------------------------------------------------
__global__ __launch_bounds__(256)
void dynfilt_kernel(const float* __restrict__ img, float* __restrict__ out)
{
    int tid = blockIdx.x * 256 + threadIdx.x;   // 8*6*512*128 threads
    int x4 = tid & 127;
    int y  = (tid >> 7) & 511;
    int bc = tid >> 16;            // b*6 + ch
    int ch = bc % 6;
    int b  = bc / 6;
    int g  = ch / 3;

    const float* wp = g_cond + (((size_t)b * C2 + g * 9) * NHW + (y >> 2)) * NHW + x4;
    float w[9];
#pragma unroll
    for (int k = 0; k < 9; ++k) w[k] = wp[(size_t)k * (NHW * NHW)];

    const float* ip = img + ((size_t)b * 6 + ch) * (HH * WW);
    int x = x4 * 4;
    float4 acc = make_float4(0.f, 0.f, 0.f, 0.f);
#pragma unroll
    for (int i = 0; i < 3; ++i) {
        int xx = x + (i - 1) * 4;
        bool xok = (unsigned)xx < (unsigned)WW;
#pragma unroll
        for (int j = 0; j < 3; ++j) {
            int yy = y + (j - 1) * 4;
            float4 v = make_float4(0.f, 0.f, 0.f, 0.f);
            if (xok && (unsigned)yy < (unsigned)HH)
                v = *(const float4*)(ip + (size_t)yy * WW + xx);
            float wk = w[i * 3 + j];
            acc.x = fmaf(v.x, wk, acc.x);
            acc.y = fmaf(v.y, wk, acc.y);
            acc.z = fmaf(v.z, wk, acc.z);
            acc.w = fmaf(v.w, wk, acc.w);
        }
    }
    *(float4*)(out + (((size_t)b * 6 + ch) * HH + y) * WW + x) = acc;
}

// ---------------------------------------------------------------------------
extern "C" void kernel_launch(void* const* d_in, const int* in_sizes, int n_in,
                              void* d_out, int out_size)
{
    const float* image = (const float*)d_in[0];
    const float* ctrl  = (const float*)d_in[1];
    const float* w1    = (const float*)d_in[2];
    const float* b1    = (const float*)d_in[3];
    const float* gamma = (const float*)d_in[4];
    const float* beta  = (const float*)d_in[5];
    const float* mean  = (const float*)d_in[6];
    const float* var   = (const float*)d_in[7];
    const float* w2    = (const float*)d_in[8];
    const float* b2    = (const float*)d_in[9];
    float* out = (float*)d_out;

    conv1_kernel<<<dim3(4, 16, BATCH), 256>>>(ctrl, w1, b1, gamma, beta, mean, var);
    conv2_kernel<<<dim3(4, 4, BATCH), 256>>>(w2, b2);
    dynfilt_kernel<<<(BATCH * 6 * HH * (WW / 4)) / 256, 256>>>(image, out);
}